// round 14
// baseline (speedup 1.0000x reference)
#include <cuda_runtime.h>
#include <cuda_bf16.h>
#include <cstdint>

// Problem constants
#define RR 2048
#define CC 2048
#define DD 64
#define OO 4
#define KP 288            // 256 z-terms + 10 pair + 1 const + 21 zero ; 9 * 32
#define NCHUNK 9          // K chunks of 32

// GEMM tiling: 128x128 CTA, 4 warps of 64x64, 2 CTAs/SM
#define BM 128
#define BN 128
#define NTHREADS 128
// smem: events tile 128 rows x 132 words (528B padded rows) = 67584 B
#define EV_STRIDE 528
#define SMEM_BYTES (128 * EV_STRIDE)

// ---------------------------------------------------------------------------
// Scratch in pre-packed bf16 tile-image layout (chunk = 128 rows x 32 bf16).
//   A: [mtile(16)][chunk(9)][128 rows][32 bf16]
//   B: [ntile(16)][chunk(9)][128 rows][32 bf16]
// Row packing for m16n8k16 fragments (rowoff16): thread (g,tg) reads its
// fragment pair for BOTH k16 groups as ONE uint4 at row*64B + tg*16B.
// GEMM loads these DIRECTLY via LDG.128 (L1-cached); no smem in mainloop.
// ---------------------------------------------------------------------------
__device__ __nv_bfloat16 g_A[(size_t)16 * NCHUNK * 4096];
__device__ __nv_bfloat16 g_B[(size_t)16 * NCHUNK * 4096];

__device__ __forceinline__ int rowoff16(int k) {
    int kk = k & 31;
    int grp = kk >> 4, j = kk & 15;
    int pr = j >> 1, w = j & 1;
    int unit = ((pr & 3) << 2) | (grp << 1) | (pr >> 2);
    return unit * 2 + w;
}

__device__ __forceinline__ size_t idxA(int r, int k) {
    int mt = r >> 7, m = r & 127, ck = k >> 5;
    return ((size_t)(mt * NCHUNK + ck) << 12) + m * 32 + rowoff16(k);
}

__device__ __forceinline__ size_t idxB(int c, int k) {
    int nt = c >> 7, n = c & 127, ck = k >> 5;
    return ((size_t)(nt * NCHUNK + ck) << 12) + n * 32 + rowoff16(k);
}

#define MMA_BF16(c, a0, a1, a2, a3, b0, b1) \
    asm volatile("mma.sync.aligned.m16n8k16.row.col.f32.bf16.bf16.f32 " \
        "{%0,%1,%2,%3}, {%4,%5,%6,%7}, {%8,%9}, {%0,%1,%2,%3};" \
        : "+f"((c)[0]), "+f"((c)[1]), "+f"((c)[2]), "+f"((c)[3]) \
        : "r"(a0), "r"(a1), "r"(a2), "r"(a3), "r"(b0), "r"(b1))

#define CP_ASYNC16(dst_u32, src_ptr) \
    asm volatile("cp.async.cg.shared.global [%0], [%1], 16;" \
                 :: "r"(dst_u32), "l"(src_ptr))

__device__ __forceinline__ float sqrt_ap(float x) {
    float y; asm("sqrt.approx.f32 %0, %1;" : "=f"(y) : "f"(x)); return y;
}
__device__ __forceinline__ float ex2_ap(float x) {
    float y; asm("ex2.approx.f32 %0, %1;" : "=f"(y) : "f"(x)); return y;
}
__device__ __forceinline__ float lg2_ap(float x) {
    float y; asm("lg2.approx.f32 %0, %1;" : "=f"(y) : "f"(x)); return y;
}

// ---------------------------------------------------------------------------
__global__ void init_out_kernel(float* out) { out[0] = 0.0f; }

// ---------------------------------------------------------------------------
// prep_rows: one warp per row r.
// ---------------------------------------------------------------------------
__global__ void prep_rows_kernel(const float* __restrict__ z_rows) {
    int gw = (blockIdx.x * blockDim.x + threadIdx.x) >> 5;
    int lane = threadIdx.x & 31;
    if (gw >= RR) return;
    int r = gw;

    float z[OO][2];
#pragma unroll
    for (int o = 0; o < OO; o++) {
#pragma unroll
        for (int j = 0; j < 2; j++) {
            int d = lane + j * 32;
            float v = z_rows[((size_t)o * RR + r) * DD + d];
            z[o][j] = v;
            g_A[idxA(r, o * DD + d)] = __float2bfloat16_rn(v);
        }
    }
    int p = 0;
#pragma unroll
    for (int o1 = 0; o1 < OO; o1++) {
#pragma unroll
        for (int o2 = o1; o2 < OO; o2++) {
            float part = z[o1][0] * z[o2][0] + z[o1][1] * z[o2][1];
#pragma unroll
            for (int off = 16; off > 0; off >>= 1)
                part += __shfl_xor_sync(0xFFFFFFFFu, part, off);
            if (lane == 0) g_A[idxA(r, 256 + p)] = __float2bfloat16_rn(part);
            p++;
        }
    }
    if (lane == 0) g_A[idxA(r, 266)] = __float2bfloat16_rn(1.0f);
    if (lane < 21) g_A[idxA(r, 267 + lane)] = __float2bfloat16_rn(0.0f);
}

// ---------------------------------------------------------------------------
// prep_cols: one warp per column c.
// ---------------------------------------------------------------------------
__global__ void prep_cols_kernel(const float* __restrict__ z_cols,
                                 const float* __restrict__ col_times) {
    int gw = (blockIdx.x * blockDim.x + threadIdx.x) >> 5;
    int lane = threadIdx.x & 31;
    if (gw >= CC) return;
    int c = gw;

    float t = col_times[c];
    float coef[OO];
    coef[0] = 1.0f;
    coef[1] = t;
    coef[2] = t * t * 0.5f;
    coef[3] = t * t * t * (1.0f / 6.0f);

    float zc[2];
    float zc2 = 0.0f;
#pragma unroll
    for (int j = 0; j < 2; j++) {
        int d = lane + j * 32;
        zc[j] = z_cols[(size_t)c * DD + d];
        zc2 += zc[j] * zc[j];
    }
#pragma unroll
    for (int off = 16; off > 0; off >>= 1)
        zc2 += __shfl_xor_sync(0xFFFFFFFFu, zc2, off);

#pragma unroll
    for (int o = 0; o < OO; o++) {
#pragma unroll
        for (int j = 0; j < 2; j++) {
            int d = lane + j * 32;
            g_B[idxB(c, o * DD + d)] = __float2bfloat16_rn(-2.0f * coef[o] * zc[j]);
        }
    }
    if (lane == 0) {
        int p = 0;
#pragma unroll
        for (int o1 = 0; o1 < OO; o1++) {
#pragma unroll
            for (int o2 = o1; o2 < OO; o2++) {
                float f = (o1 == o2) ? 1.0f : 2.0f;
                g_B[idxB(c, 256 + p)] = __float2bfloat16_rn(f * coef[o1] * coef[o2]);
                p++;
            }
        }
        g_B[idxB(c, 266)] = __float2bfloat16_rn(zc2);
    }
    if (lane < 21) g_B[idxB(c, 267 + lane)] = __float2bfloat16_rn(0.0f);
}

// ---------------------------------------------------------------------------
// bf16 mma.sync GEMM, fragments loaded DIRECTLY from gmem (no smem/barriers
// in mainloop). Events tile (64KB) prefetched to smem via cp.async.cg at
// kernel entry, overlapping the ENTIRE mainloop; epilogue reads smem.
// 4 warps of 64x64, 2 CTAs/SM, fused log2-domain epilogue.
// ---------------------------------------------------------------------------
__global__ void __launch_bounds__(NTHREADS, 2)
gemm_mma_kernel(const int* __restrict__ events,
                const float* __restrict__ gamma_rows,
                const float* __restrict__ gamma_cols,
                float* __restrict__ out) {
    extern __shared__ char smem[];
    const int tid  = threadIdx.x;
    const int wid  = tid >> 5;
    const int lane = tid & 31;
    const int wm   = wid >> 1;          // 0..1
    const int wn   = wid & 1;           // 0..1
    const int g    = lane >> 2;         // 0..7
    const int tg   = lane & 3;          // 0..3

    // ---- kick off events-tile prefetch (overlaps whole mainloop) ----
    {
        const uint32_t evs = (uint32_t)__cvta_generic_to_shared(smem);
        const char* src0 = (const char*)events
                         + ((size_t)(blockIdx.y * BM)) * (CC * 4)
                         + (size_t)(blockIdx.x * BN) * 4;
#pragma unroll
        for (int i = 0; i < 32; i++) {
            int u = tid + i * 128;           // 4096 16B units
            int row = u >> 5, c16 = u & 31;  // warp-per-row: coalesced 512B
            CP_ASYNC16(evs + row * EV_STRIDE + c16 * 16,
                       src0 + (size_t)row * (CC * 4) + c16 * 16);
        }
        asm volatile("cp.async.commit_group;");
    }

    const uint4* __restrict__ paBase = (const uint4*)(
        g_A + ((size_t)(blockIdx.y * NCHUNK) << 12) + (wm * 64 + g) * 32 + tg * 8);
    const uint4* __restrict__ pbBase = (const uint4*)(
        g_B + ((size_t)(blockIdx.x * NCHUNK) << 12) + (wn * 64 + g) * 32 + tg * 8);

    float acc[4][8][4];
#pragma unroll
    for (int mf = 0; mf < 4; mf++)
#pragma unroll
        for (int nf = 0; nf < 8; nf++)
#pragma unroll
            for (int q = 0; q < 4; q++)
                acc[mf][nf][q] = 0.0f;

    // Fully unrolled mainloop: 16 independent LDG.128 per chunk feed 64 HMMAs.
    // Chunk 8's second k16 group covers k in [272,288) — all zero padding —
    // so its 32 HMMAs are skipped.
#pragma unroll
    for (int ck = 0; ck < NCHUNK; ck++) {
        const uint4* pa = paBase + ck * 512;
        const uint4* pb = pbBase + ck * 512;
        uint4 alo[4], ahi[4], bv[8];
#pragma unroll
        for (int mf = 0; mf < 4; mf++) {
            alo[mf] = __ldg(pa + mf * 64);
            ahi[mf] = __ldg(pa + mf * 64 + 32);
        }
#pragma unroll
        for (int nf = 0; nf < 8; nf++)
            bv[nf] = __ldg(pb + nf * 32);
#pragma unroll
        for (int mf = 0; mf < 4; mf++)
#pragma unroll
            for (int nf = 0; nf < 8; nf++) {
                MMA_BF16(acc[mf][nf], alo[mf].x, ahi[mf].x, alo[mf].y,
                         ahi[mf].y, bv[nf].x, bv[nf].y);
                if (ck != NCHUNK - 1)
                    MMA_BF16(acc[mf][nf], alo[mf].z, ahi[mf].z, alo[mf].w,
                             ahi[mf].w, bv[nf].z, bv[nf].w);
            }
    }

    // ---- events now resident in smem ----
    asm volatile("cp.async.wait_group 0;" ::: "memory");
    __syncthreads();

    // ---- fused epilogue (log2 domain, smem events) ----
    const float L2E = 1.4426950408889634f;
    const float C2  = L2E * L2E;
    const int rbase = blockIdx.y * BM + wm * 64;
    const int cbase = blockIdx.x * BN + wn * 64;
    const int lr    = wm * 64;           // local row base in smem tile
    const int lc    = wn * 64;           // local col base

    float accSU = 0.0f, accAB = 0.0f, accLG = 0.0f;
#pragma unroll
    for (int mf = 0; mf < 4; mf++) {
        const int r0 = rbase + mf * 16 + g;
        const int sr0 = lr + mf * 16 + g;
        const float gr0 = gamma_rows[r0] * L2E;
        const float gr1 = gamma_rows[r0 + 8] * L2E;
#pragma unroll
        for (int nf = 0; nf < 8; nf++) {
            const int cc = cbase + nf * 8 + tg * 2;
            const int sc = lc + nf * 8 + tg * 2;
            const float gc0 = gamma_cols[cc] * L2E;
            const float gc1 = gamma_cols[cc + 1] * L2E;
            int2 e0 = *(const int2*)(smem + sr0 * EV_STRIDE + sc * 4);
            int2 e1 = *(const int2*)(smem + (sr0 + 8) * EV_STRIDE + sc * 4);
            const float* d = acc[mf][nf];
            float gs[4] = {gr0 + gc0, gr0 + gc1, gr1 + gc0, gr1 + gc1};
            int   ev[4] = {e0.x, e0.y, e1.x, e1.y};
            float prod = 1.0f;
#pragma unroll
            for (int q = 0; q < 4; q++) {
                float dd = fmaxf(d[q] * C2, 0.0f);
                float u2 = gs[q] - sqrt_ap(dd);
                float au = fabsf(u2);
                accSU += ev[q] ? u2 : -u2;
                accAB += au;
                float t = ex2_ap(-au);
                prod = fmaf(prod, t, prod);
            }
            accLG += lg2_ap(prod);
        }
    }
    float lsum = 0.69314718056f * (0.5f * (accSU - accAB) - accLG);
#pragma unroll
    for (int off = 16; off > 0; off >>= 1)
        lsum += __shfl_xor_sync(0xFFFFFFFFu, lsum, off);
    if (lane == 0) atomicAdd(out, -lsum);
}

// ---------------------------------------------------------------------------
// launch
// ---------------------------------------------------------------------------
extern "C" void kernel_launch(void* const* d_in, const int* in_sizes, int n_in,
                              void* d_out, int out_size) {
    const int*   events     = (const int*)d_in[0];
    const float* col_times  = (const float*)d_in[1];
    const float* z_rows     = (const float*)d_in[2];
    const float* z_cols     = (const float*)d_in[3];
    const float* gamma_rows = (const float*)d_in[4];
    const float* gamma_cols = (const float*)d_in[5];
    float* out = (float*)d_out;

    static int configured = 0;
    if (!configured) {
        cudaFuncSetAttribute(gemm_mma_kernel,
                             cudaFuncAttributeMaxDynamicSharedMemorySize,
                             SMEM_BYTES);
        configured = 1;
    }

    init_out_kernel<<<1, 1>>>(out);
    prep_rows_kernel<<<RR / 8, 256>>>(z_rows);
    prep_cols_kernel<<<CC / 8, 256>>>(z_cols, col_times);

    dim3 grid(CC / BN, RR / BM);   // (16, 16)
    gemm_mma_kernel<<<grid, NTHREADS, SMEM_BYTES>>>(events, gamma_rows,
                                                    gamma_cols, out);
}

// round 15
// speedup vs baseline: 1.0015x; 1.0015x over previous
#include <cuda_runtime.h>
#include <cuda_bf16.h>
#include <cstdint>

// Problem constants
#define RR 2048
#define CC 2048
#define DD 64
#define OO 4
#define KP 288            // 256 z-terms + 10 pair + 1 const + 21 zero ; 9 * 32
#define NCHUNK 9          // K chunks of 32

// GEMM tiling: 128x128 CTA, 4 warps of 64x64, 2 CTAs/SM
#define BM 128
#define BN 128
#define NTHREADS 128
// smem: events tile 128 rows x 132 words (528B padded rows) = 67584 B
#define EV_STRIDE 528
#define SMEM_BYTES (128 * EV_STRIDE)

// ---------------------------------------------------------------------------
// Scratch in pre-packed bf16 tile-image layout (chunk = 128 rows x 32 bf16).
//   A: [mtile(16)][chunk(9)][128 rows][32 bf16]
//   B: [ntile(16)][chunk(9)][128 rows][32 bf16]
// Row packing for m16n8k16 fragments (rowoff16): thread (g,tg) reads its
// fragment pair for BOTH k16 groups as ONE uint4 at row*64B + tg*16B.
// GEMM loads these DIRECTLY via LDG.128; no smem in the MMA path.
// ---------------------------------------------------------------------------
__device__ __nv_bfloat16 g_A[(size_t)16 * NCHUNK * 4096];
__device__ __nv_bfloat16 g_B[(size_t)16 * NCHUNK * 4096];

__device__ __forceinline__ int rowoff16(int k) {
    int kk = k & 31;
    int grp = kk >> 4, j = kk & 15;
    int pr = j >> 1, w = j & 1;
    int unit = ((pr & 3) << 2) | (grp << 1) | (pr >> 2);
    return unit * 2 + w;
}

__device__ __forceinline__ size_t idxA(int r, int k) {
    int mt = r >> 7, m = r & 127, ck = k >> 5;
    return ((size_t)(mt * NCHUNK + ck) << 12) + m * 32 + rowoff16(k);
}

__device__ __forceinline__ size_t idxB(int c, int k) {
    int nt = c >> 7, n = c & 127, ck = k >> 5;
    return ((size_t)(nt * NCHUNK + ck) << 12) + n * 32 + rowoff16(k);
}

#define MMA_BF16(c, a0, a1, a2, a3, b0, b1) \
    asm volatile("mma.sync.aligned.m16n8k16.row.col.f32.bf16.bf16.f32 " \
        "{%0,%1,%2,%3}, {%4,%5,%6,%7}, {%8,%9}, {%0,%1,%2,%3};" \
        : "+f"((c)[0]), "+f"((c)[1]), "+f"((c)[2]), "+f"((c)[3]) \
        : "r"(a0), "r"(a1), "r"(a2), "r"(a3), "r"(b0), "r"(b1))

#define CP_ASYNC16(dst_u32, src_ptr) \
    asm volatile("cp.async.cg.shared.global [%0], [%1], 16;" \
                 :: "r"(dst_u32), "l"(src_ptr))

__device__ __forceinline__ float sqrt_ap(float x) {
    float y; asm("sqrt.approx.f32 %0, %1;" : "=f"(y) : "f"(x)); return y;
}
__device__ __forceinline__ float ex2_ap(float x) {
    float y; asm("ex2.approx.f32 %0, %1;" : "=f"(y) : "f"(x)); return y;
}
__device__ __forceinline__ float lg2_ap(float x) {
    float y; asm("lg2.approx.f32 %0, %1;" : "=f"(y) : "f"(x)); return y;
}

// ---------------------------------------------------------------------------
__global__ void init_out_kernel(float* out) { out[0] = 0.0f; }

// ---------------------------------------------------------------------------
// prep_rows: one warp per row r.
// ---------------------------------------------------------------------------
__global__ void prep_rows_kernel(const float* __restrict__ z_rows) {
    int gw = (blockIdx.x * blockDim.x + threadIdx.x) >> 5;
    int lane = threadIdx.x & 31;
    if (gw >= RR) return;
    int r = gw;

    float z[OO][2];
#pragma unroll
    for (int o = 0; o < OO; o++) {
#pragma unroll
        for (int j = 0; j < 2; j++) {
            int d = lane + j * 32;
            float v = z_rows[((size_t)o * RR + r) * DD + d];
            z[o][j] = v;
            g_A[idxA(r, o * DD + d)] = __float2bfloat16_rn(v);
        }
    }
    int p = 0;
#pragma unroll
    for (int o1 = 0; o1 < OO; o1++) {
#pragma unroll
        for (int o2 = o1; o2 < OO; o2++) {
            float part = z[o1][0] * z[o2][0] + z[o1][1] * z[o2][1];
#pragma unroll
            for (int off = 16; off > 0; off >>= 1)
                part += __shfl_xor_sync(0xFFFFFFFFu, part, off);
            if (lane == 0) g_A[idxA(r, 256 + p)] = __float2bfloat16_rn(part);
            p++;
        }
    }
    if (lane == 0) g_A[idxA(r, 266)] = __float2bfloat16_rn(1.0f);
    if (lane < 21) g_A[idxA(r, 267 + lane)] = __float2bfloat16_rn(0.0f);
}

// ---------------------------------------------------------------------------
// prep_cols: one warp per column c.
// ---------------------------------------------------------------------------
__global__ void prep_cols_kernel(const float* __restrict__ z_cols,
                                 const float* __restrict__ col_times) {
    int gw = (blockIdx.x * blockDim.x + threadIdx.x) >> 5;
    int lane = threadIdx.x & 31;
    if (gw >= CC) return;
    int c = gw;

    float t = col_times[c];
    float coef[OO];
    coef[0] = 1.0f;
    coef[1] = t;
    coef[2] = t * t * 0.5f;
    coef[3] = t * t * t * (1.0f / 6.0f);

    float zc[2];
    float zc2 = 0.0f;
#pragma unroll
    for (int j = 0; j < 2; j++) {
        int d = lane + j * 32;
        zc[j] = z_cols[(size_t)c * DD + d];
        zc2 += zc[j] * zc[j];
    }
#pragma unroll
    for (int off = 16; off > 0; off >>= 1)
        zc2 += __shfl_xor_sync(0xFFFFFFFFu, zc2, off);

#pragma unroll
    for (int o = 0; o < OO; o++) {
#pragma unroll
        for (int j = 0; j < 2; j++) {
            int d = lane + j * 32;
            g_B[idxB(c, o * DD + d)] = __float2bfloat16_rn(-2.0f * coef[o] * zc[j]);
        }
    }
    if (lane == 0) {
        int p = 0;
#pragma unroll
        for (int o1 = 0; o1 < OO; o1++) {
#pragma unroll
            for (int o2 = o1; o2 < OO; o2++) {
                float f = (o1 == o2) ? 1.0f : 2.0f;
                g_B[idxB(c, 256 + p)] = __float2bfloat16_rn(f * coef[o1] * coef[o2]);
                p++;
            }
        }
        g_B[idxB(c, 266)] = __float2bfloat16_rn(zc2);
    }
    if (lane < 21) g_B[idxB(c, 267 + lane)] = __float2bfloat16_rn(0.0f);
}

// ---------------------------------------------------------------------------
// bf16 mma.sync GEMM, fragments loaded DIRECTLY from gmem. Events tile
// prefetched to smem via cp.async.cg SPREAD across mainloop chunks (4 per
// thread per chunk, issued AFTER the chunk's fragment loads so they never
// block the critical path). 4 warps of 64x64, 2 CTAs/SM.
// Chunk 8's second k16 group (k in [272,288)) is zero padding: its 32 HMMAs
// are skipped by peeling the tail OUTSIDE the loop (no branch in MMA nest).
// ---------------------------------------------------------------------------
__global__ void __launch_bounds__(NTHREADS, 2)
gemm_mma_kernel(const int* __restrict__ events,
                const float* __restrict__ gamma_rows,
                const float* __restrict__ gamma_cols,
                float* __restrict__ out) {
    extern __shared__ char smem[];
    const int tid  = threadIdx.x;
    const int wid  = tid >> 5;
    const int lane = tid & 31;
    const int wm   = wid >> 1;          // 0..1
    const int wn   = wid & 1;           // 0..1
    const int g    = lane >> 2;         // 0..7
    const int tg   = lane & 3;          // 0..3

    const uint32_t evs = (uint32_t)__cvta_generic_to_shared(smem);
    const char* evsrc = (const char*)events
                      + ((size_t)(blockIdx.y * BM)) * (CC * 4)
                      + (size_t)(blockIdx.x * BN) * 4;

    const uint4* __restrict__ paBase = (const uint4*)(
        g_A + ((size_t)(blockIdx.y * NCHUNK) << 12) + (wm * 64 + g) * 32 + tg * 8);
    const uint4* __restrict__ pbBase = (const uint4*)(
        g_B + ((size_t)(blockIdx.x * NCHUNK) << 12) + (wn * 64 + g) * 32 + tg * 8);

    float acc[4][8][4];
#pragma unroll
    for (int mf = 0; mf < 4; mf++)
#pragma unroll
        for (int nf = 0; nf < 8; nf++)
#pragma unroll
            for (int q = 0; q < 4; q++)
                acc[mf][nf][q] = 0.0f;

    // ---- mainloop: chunks 0..7 (full), events prefetch interleaved ----
#pragma unroll
    for (int ck = 0; ck < NCHUNK - 1; ck++) {
        const uint4* pa = paBase + ck * 512;
        const uint4* pb = pbBase + ck * 512;
        uint4 alo[4], ahi[4], bv[8];
#pragma unroll
        for (int mf = 0; mf < 4; mf++) {
            alo[mf] = __ldg(pa + mf * 64);
            ahi[mf] = __ldg(pa + mf * 64 + 32);
        }
#pragma unroll
        for (int nf = 0; nf < 8; nf++)
            bv[nf] = __ldg(pb + nf * 32);

        // events prefetch slice: 4 x 16B per thread per chunk (behind the
        // fragment loads in the L1tex queue; done long before the epilogue)
#pragma unroll
        for (int i = 0; i < 4; i++) {
            int u = tid + (ck * 4 + i) * 128;    // 0..4095
            int row = u >> 5, c16 = u & 31;
            CP_ASYNC16(evs + row * EV_STRIDE + c16 * 16,
                       evsrc + (size_t)row * (CC * 4) + c16 * 16);
        }

#pragma unroll
        for (int mf = 0; mf < 4; mf++)
#pragma unroll
            for (int nf = 0; nf < 8; nf++) {
                MMA_BF16(acc[mf][nf], alo[mf].x, ahi[mf].x, alo[mf].y,
                         ahi[mf].y, bv[nf].x, bv[nf].y);
                MMA_BF16(acc[mf][nf], alo[mf].z, ahi[mf].z, alo[mf].w,
                         ahi[mf].w, bv[nf].z, bv[nf].w);
            }
    }

    // ---- tail chunk 8: only first k16 group (second is zero padding) ----
    {
        const uint4* pa = paBase + (NCHUNK - 1) * 512;
        const uint4* pb = pbBase + (NCHUNK - 1) * 512;
        uint4 alo[4], ahi[4], bv[8];
#pragma unroll
        for (int mf = 0; mf < 4; mf++) {
            alo[mf] = __ldg(pa + mf * 64);
            ahi[mf] = __ldg(pa + mf * 64 + 32);
        }
#pragma unroll
        for (int nf = 0; nf < 8; nf++)
            bv[nf] = __ldg(pb + nf * 32);
#pragma unroll
        for (int mf = 0; mf < 4; mf++)
#pragma unroll
            for (int nf = 0; nf < 8; nf++)
                MMA_BF16(acc[mf][nf], alo[mf].x, ahi[mf].x, alo[mf].y,
                         ahi[mf].y, bv[nf].x, bv[nf].y);
    }

    asm volatile("cp.async.wait_all;" ::: "memory");
    __syncthreads();

    // ---- fused epilogue (log2 domain, smem events) ----
    const float L2E = 1.4426950408889634f;
    const float C2  = L2E * L2E;
    const int rbase = blockIdx.y * BM + wm * 64;
    const int cbase = blockIdx.x * BN + wn * 64;
    const int lr    = wm * 64;
    const int lc    = wn * 64;

    float accSU = 0.0f, accAB = 0.0f, accLG = 0.0f;
#pragma unroll
    for (int mf = 0; mf < 4; mf++) {
        const int r0 = rbase + mf * 16 + g;
        const int sr0 = lr + mf * 16 + g;
        const float gr0 = gamma_rows[r0] * L2E;
        const float gr1 = gamma_rows[r0 + 8] * L2E;
#pragma unroll
        for (int nf = 0; nf < 8; nf++) {
            const int cc = cbase + nf * 8 + tg * 2;
            const int sc = lc + nf * 8 + tg * 2;
            const float gc0 = gamma_cols[cc] * L2E;
            const float gc1 = gamma_cols[cc + 1] * L2E;
            int2 e0 = *(const int2*)(smem + sr0 * EV_STRIDE + sc * 4);
            int2 e1 = *(const int2*)(smem + (sr0 + 8) * EV_STRIDE + sc * 4);
            const float* d = acc[mf][nf];
            float gs[4] = {gr0 + gc0, gr0 + gc1, gr1 + gc0, gr1 + gc1};
            int   ev[4] = {e0.x, e0.y, e1.x, e1.y};
            float prod = 1.0f;
#pragma unroll
            for (int q = 0; q < 4; q++) {
                float dd = fmaxf(d[q] * C2, 0.0f);
                float u2 = gs[q] - sqrt_ap(dd);
                float au = fabsf(u2);
                accSU += ev[q] ? u2 : -u2;
                accAB += au;
                float t = ex2_ap(-au);
                prod = fmaf(prod, t, prod);
            }
            accLG += lg2_ap(prod);
        }
    }
    float lsum = 0.69314718056f * (0.5f * (accSU - accAB) - accLG);
#pragma unroll
    for (int off = 16; off > 0; off >>= 1)
        lsum += __shfl_xor_sync(0xFFFFFFFFu, lsum, off);
    if (lane == 0) atomicAdd(out, -lsum);
}

// ---------------------------------------------------------------------------
// launch
// ---------------------------------------------------------------------------
extern "C" void kernel_launch(void* const* d_in, const int* in_sizes, int n_in,
                              void* d_out, int out_size) {
    const int*   events     = (const int*)d_in[0];
    const float* col_times  = (const float*)d_in[1];
    const float* z_rows     = (const float*)d_in[2];
    const float* z_cols     = (const float*)d_in[3];
    const float* gamma_rows = (const float*)d_in[4];
    const float* gamma_cols = (const float*)d_in[5];
    float* out = (float*)d_out;

    static int configured = 0;
    if (!configured) {
        cudaFuncSetAttribute(gemm_mma_kernel,
                             cudaFuncAttributeMaxDynamicSharedMemorySize,
                             SMEM_BYTES);
        configured = 1;
    }

    init_out_kernel<<<1, 1>>>(out);
    prep_rows_kernel<<<RR / 8, 256>>>(z_rows);
    prep_cols_kernel<<<CC / 8, 256>>>(z_cols, col_times);

    dim3 grid(CC / BN, RR / BM);   // (16, 16)
    gemm_mma_kernel<<<grid, NTHREADS, SMEM_BYTES>>>(events, gamma_rows,
                                                    gamma_cols, out);
}

// round 16
// speedup vs baseline: 1.1067x; 1.1050x over previous
#include <cuda_runtime.h>
#include <cuda_bf16.h>
#include <cstdint>

// Problem constants
#define RR 2048
#define CC 2048
#define DD 64
#define OO 4
#define KP 288            // 256 z-terms + 10 pair + 1 const + 21 zero ; 9 * 32
#define NCHUNK 9          // K chunks of 32

// GEMM tiling: 128x128 CTA, 4 warps of 64x64, 2 CTAs/SM, NO shared memory
#define BM 128
#define BN 128
#define NTHREADS 128

// ---------------------------------------------------------------------------
// Scratch in pre-packed bf16 tile-image layout (chunk = 128 rows x 32 bf16).
//   A: [mtile(16)][chunk(9)][128 rows][32 bf16]
//   B: [ntile(16)][chunk(9)][128 rows][32 bf16]
// Row packing for m16n8k16 fragments (rowoff16): thread (g,tg) reads its
// fragment pair for BOTH k16 groups as ONE uint4 at row*64B + tg*16B
// (.x/.y = first k16 group, .z/.w = second). GEMM loads these DIRECTLY via
// LDG.128 (L1-cached); no smem, no barriers.
// ---------------------------------------------------------------------------
__device__ __nv_bfloat16 g_A[(size_t)16 * NCHUNK * 4096];
__device__ __nv_bfloat16 g_B[(size_t)16 * NCHUNK * 4096];

__device__ __forceinline__ int rowoff16(int k) {
    int kk = k & 31;
    int grp = kk >> 4, j = kk & 15;
    int pr = j >> 1, w = j & 1;
    int unit = ((pr & 3) << 2) | (grp << 1) | (pr >> 2);
    return unit * 2 + w;
}

__device__ __forceinline__ size_t idxA(int r, int k) {
    int mt = r >> 7, m = r & 127, ck = k >> 5;
    return ((size_t)(mt * NCHUNK + ck) << 12) + m * 32 + rowoff16(k);
}

__device__ __forceinline__ size_t idxB(int c, int k) {
    int nt = c >> 7, n = c & 127, ck = k >> 5;
    return ((size_t)(nt * NCHUNK + ck) << 12) + n * 32 + rowoff16(k);
}

#define MMA_BF16(c, a0, a1, a2, a3, b0, b1) \
    asm volatile("mma.sync.aligned.m16n8k16.row.col.f32.bf16.bf16.f32 " \
        "{%0,%1,%2,%3}, {%4,%5,%6,%7}, {%8,%9}, {%0,%1,%2,%3};" \
        : "+f"((c)[0]), "+f"((c)[1]), "+f"((c)[2]), "+f"((c)[3]) \
        : "r"(a0), "r"(a1), "r"(a2), "r"(a3), "r"(b0), "r"(b1))

__device__ __forceinline__ float sqrt_ap(float x) {
    float y; asm("sqrt.approx.f32 %0, %1;" : "=f"(y) : "f"(x)); return y;
}
__device__ __forceinline__ float ex2_ap(float x) {
    float y; asm("ex2.approx.f32 %0, %1;" : "=f"(y) : "f"(x)); return y;
}
__device__ __forceinline__ float lg2_ap(float x) {
    float y; asm("lg2.approx.f32 %0, %1;" : "=f"(y) : "f"(x)); return y;
}

// ---------------------------------------------------------------------------
// Merged prep kernel: 512 blocks x 256 threads.
//   blocks [0,256):   A rows (1 row per warp); block 0 thread 0 zeroes out[0]
//   blocks [256,512): B cols (1 col per warp)
// ---------------------------------------------------------------------------
__global__ void prep_all_kernel(const float* __restrict__ z_rows,
                                const float* __restrict__ z_cols,
                                const float* __restrict__ col_times,
                                float* __restrict__ out) {
    const int bid  = blockIdx.x;
    const int wid  = threadIdx.x >> 5;
    const int lane = threadIdx.x & 31;

    if (bid == 0 && threadIdx.x == 0) out[0] = 0.0f;

    if (bid < 256) {
        // ---- rows ----
        int r = bid * 8 + wid;
        float z[OO][2];
#pragma unroll
        for (int o = 0; o < OO; o++) {
#pragma unroll
            for (int j = 0; j < 2; j++) {
                int d = lane + j * 32;
                float v = z_rows[((size_t)o * RR + r) * DD + d];
                z[o][j] = v;
                g_A[idxA(r, o * DD + d)] = __float2bfloat16_rn(v);
            }
        }
        int p = 0;
#pragma unroll
        for (int o1 = 0; o1 < OO; o1++) {
#pragma unroll
            for (int o2 = o1; o2 < OO; o2++) {
                float part = z[o1][0] * z[o2][0] + z[o1][1] * z[o2][1];
#pragma unroll
                for (int off = 16; off > 0; off >>= 1)
                    part += __shfl_xor_sync(0xFFFFFFFFu, part, off);
                if (lane == 0) g_A[idxA(r, 256 + p)] = __float2bfloat16_rn(part);
                p++;
            }
        }
        if (lane == 0) g_A[idxA(r, 266)] = __float2bfloat16_rn(1.0f);
        if (lane < 21) g_A[idxA(r, 267 + lane)] = __float2bfloat16_rn(0.0f);
    } else {
        // ---- cols ----
        int c = (bid - 256) * 8 + wid;
        float t = col_times[c];
        float coef[OO];
        coef[0] = 1.0f;
        coef[1] = t;
        coef[2] = t * t * 0.5f;
        coef[3] = t * t * t * (1.0f / 6.0f);

        float zc[2];
        float zc2 = 0.0f;
#pragma unroll
        for (int j = 0; j < 2; j++) {
            int d = lane + j * 32;
            zc[j] = z_cols[(size_t)c * DD + d];
            zc2 += zc[j] * zc[j];
        }
#pragma unroll
        for (int off = 16; off > 0; off >>= 1)
            zc2 += __shfl_xor_sync(0xFFFFFFFFu, zc2, off);

#pragma unroll
        for (int o = 0; o < OO; o++) {
#pragma unroll
            for (int j = 0; j < 2; j++) {
                int d = lane + j * 32;
                g_B[idxB(c, o * DD + d)] = __float2bfloat16_rn(-2.0f * coef[o] * zc[j]);
            }
        }
        if (lane == 0) {
            int p = 0;
#pragma unroll
            for (int o1 = 0; o1 < OO; o1++) {
#pragma unroll
                for (int o2 = o1; o2 < OO; o2++) {
                    float f = (o1 == o2) ? 1.0f : 2.0f;
                    g_B[idxB(c, 256 + p)] = __float2bfloat16_rn(f * coef[o1] * coef[o2]);
                    p++;
                }
            }
            g_B[idxB(c, 266)] = __float2bfloat16_rn(zc2);
        }
        if (lane < 21) g_B[idxB(c, 267 + lane)] = __float2bfloat16_rn(0.0f);
    }
}

// ---------------------------------------------------------------------------
// bf16 mma.sync GEMM, fragments loaded DIRECTLY from gmem (no smem/barriers),
// + fused log2-domain epilogue with direct int2 events reads.
// Chunk 8's second k16 group (k in [272,288)) is zero padding: skipped via
// a peeled tail block (no branch in the MMA nest).
// ---------------------------------------------------------------------------
__global__ void __launch_bounds__(NTHREADS, 2)
gemm_mma_kernel(const int* __restrict__ events,
                const float* __restrict__ gamma_rows,
                const float* __restrict__ gamma_cols,
                float* __restrict__ out) {
    const int tid  = threadIdx.x;
    const int wid  = tid >> 5;
    const int lane = tid & 31;
    const int wm   = wid >> 1;          // 0..1
    const int wn   = wid & 1;           // 0..1
    const int g    = lane >> 2;         // 0..7
    const int tg   = lane & 3;          // 0..3

    const uint4* __restrict__ paBase = (const uint4*)(
        g_A + ((size_t)(blockIdx.y * NCHUNK) << 12) + (wm * 64 + g) * 32 + tg * 8);
    const uint4* __restrict__ pbBase = (const uint4*)(
        g_B + ((size_t)(blockIdx.x * NCHUNK) << 12) + (wn * 64 + g) * 32 + tg * 8);

    float acc[4][8][4];
#pragma unroll
    for (int mf = 0; mf < 4; mf++)
#pragma unroll
        for (int nf = 0; nf < 8; nf++)
#pragma unroll
            for (int q = 0; q < 4; q++)
                acc[mf][nf][q] = 0.0f;

    // Fully unrolled mainloop (chunks 0..7): 16 independent LDG.128 per chunk
    // feed 64 HMMAs; no syncs anywhere.
#pragma unroll
    for (int ck = 0; ck < NCHUNK - 1; ck++) {
        const uint4* pa = paBase + ck * 512;
        const uint4* pb = pbBase + ck * 512;
        uint4 alo[4], ahi[4], bv[8];
#pragma unroll
        for (int mf = 0; mf < 4; mf++) {
            alo[mf] = __ldg(pa + mf * 64);        // +16 rows per mf
            ahi[mf] = __ldg(pa + mf * 64 + 32);   // +8 rows
        }
#pragma unroll
        for (int nf = 0; nf < 8; nf++)
            bv[nf] = __ldg(pb + nf * 32);         // +8 rows per nf
#pragma unroll
        for (int mf = 0; mf < 4; mf++)
#pragma unroll
            for (int nf = 0; nf < 8; nf++) {
                MMA_BF16(acc[mf][nf], alo[mf].x, ahi[mf].x, alo[mf].y,
                         ahi[mf].y, bv[nf].x, bv[nf].y);
                MMA_BF16(acc[mf][nf], alo[mf].z, ahi[mf].z, alo[mf].w,
                         ahi[mf].w, bv[nf].z, bv[nf].w);
            }
    }

    // ---- tail chunk 8: only first k16 group (second is zero padding) ----
    {
        const uint4* pa = paBase + (NCHUNK - 1) * 512;
        const uint4* pb = pbBase + (NCHUNK - 1) * 512;
        uint4 alo[4], ahi[4], bv[8];
#pragma unroll
        for (int mf = 0; mf < 4; mf++) {
            alo[mf] = __ldg(pa + mf * 64);
            ahi[mf] = __ldg(pa + mf * 64 + 32);
        }
#pragma unroll
        for (int nf = 0; nf < 8; nf++)
            bv[nf] = __ldg(pb + nf * 32);
#pragma unroll
        for (int mf = 0; mf < 4; mf++)
#pragma unroll
            for (int nf = 0; nf < 8; nf++)
                MMA_BF16(acc[mf][nf], alo[mf].x, ahi[mf].x, alo[mf].y,
                         ahi[mf].y, bv[nf].x, bv[nf].y);
    }

    // ---- fused epilogue (log2 domain, direct events reads) ----
    // sum log_sigmoid(s*(gr+gc-dist))
    //   = ln2 * [ 0.5*(sum s*u2 - sum |u2|) - sum log2(prod (1+2^-|u2|)) ]
    // product accumulated over 8 elements (two nf iterations) per LG2.
    const float L2E = 1.4426950408889634f;
    const float C2  = L2E * L2E;
    const int rbase = blockIdx.y * BM + wm * 64;
    const int cbase = blockIdx.x * BN + wn * 64;

    float accSU = 0.0f, accAB = 0.0f, accLG = 0.0f;
#pragma unroll
    for (int mf = 0; mf < 4; mf++) {
        const int r0 = rbase + mf * 16 + g;
        const float gr0 = gamma_rows[r0] * L2E;
        const float gr1 = gamma_rows[r0 + 8] * L2E;
        float prod = 1.0f;
#pragma unroll
        for (int nf = 0; nf < 8; nf++) {
            const int cc = cbase + nf * 8 + tg * 2;
            const float gc0 = gamma_cols[cc] * L2E;
            const float gc1 = gamma_cols[cc + 1] * L2E;
            int2 e0 = *(const int2*)(events + (size_t)r0 * CC + cc);
            int2 e1 = *(const int2*)(events + (size_t)(r0 + 8) * CC + cc);
            const float* d = acc[mf][nf];
            float gs[4] = {gr0 + gc0, gr0 + gc1, gr1 + gc0, gr1 + gc1};
            int   ev[4] = {e0.x, e0.y, e1.x, e1.y};
#pragma unroll
            for (int q = 0; q < 4; q++) {
                float dd = fmaxf(d[q] * C2, 0.0f);
                float u2 = gs[q] - sqrt_ap(dd);
                float au = fabsf(u2);
                accSU += ev[q] ? u2 : -u2;
                accAB += au;
                float t = ex2_ap(-au);
                prod = fmaf(prod, t, prod);
            }
            if (nf & 1) {                 // one LG2 per 8 elements
                accLG += lg2_ap(prod);
                prod = 1.0f;
            }
        }
    }
    float lsum = 0.69314718056f * (0.5f * (accSU - accAB) - accLG);
#pragma unroll
    for (int off = 16; off > 0; off >>= 1)
        lsum += __shfl_xor_sync(0xFFFFFFFFu, lsum, off);
    if (lane == 0) atomicAdd(out, -lsum);
}

// ---------------------------------------------------------------------------
// launch: just TWO kernels
// ---------------------------------------------------------------------------
extern "C" void kernel_launch(void* const* d_in, const int* in_sizes, int n_in,
                              void* d_out, int out_size) {
    const int*   events     = (const int*)d_in[0];
    const float* col_times  = (const float*)d_in[1];
    const float* z_rows     = (const float*)d_in[2];
    const float* z_cols     = (const float*)d_in[3];
    const float* gamma_rows = (const float*)d_in[4];
    const float* gamma_cols = (const float*)d_in[5];
    float* out = (float*)d_out;

    prep_all_kernel<<<512, 256>>>(z_rows, z_cols, col_times, out);

    dim3 grid(CC / BN, RR / BM);   // (16, 16)
    gemm_mma_kernel<<<grid, NTHREADS>>>(events, gamma_rows, gamma_cols, out);
}